// round 2
// baseline (speedup 1.0000x reference)
#include <cuda_runtime.h>
#include <math.h>

// ---------------- problem constants ----------------
constexpr int Bb   = 32;
constexpr int N1   = 256;
constexpr int D1   = 256;
constexpr int NH   = 8;
constexpr int KD   = 256;
constexpr int HID  = 1024;
constexpr int LAY  = 8;
constexpr int ROWS = Bb * N1;      // 8192
constexpr int QC   = NH * KD;      // 2048
constexpr float LN_EPS = 1e-3f;

// ---------------- scratch (static device memory; no allocation) ----------------
__device__ float g_patch[ROWS * D1];        // 8 MiB
__device__ float g_enc  [ROWS * D1];        // 8 MiB
__device__ float g_q    [ROWS * QC];        // 64 MiB
__device__ float g_k    [ROWS * QC];        // 64 MiB
__device__ float g_v    [ROWS * QC];        // 64 MiB
__device__ float g_attn [Bb * NH * N1 * N1];// 64 MiB
__device__ float g_o    [ROWS * QC];        // 64 MiB
__device__ float g_a    [ROWS * D1];        // 8 MiB
__device__ float g_f1   [ROWS * HID];       // 32 MiB

// ---------------- generic tiled SGEMM ----------------
// C[z] = act( alpha * A[z] @ op(B[z]) + bias )
// A: [M,K] row-major (lda).  B: NN -> [K,N] (ldb);  NT -> [N,K] (ldb), computes A.B^T
// batch index z = z1*nb2 + z2; per-operand offsets z1*s?1 + z2*s?2.
#define BM 128
#define BN 128
#define BK 16

__device__ __forceinline__ float gelu_exact(float x) {
    return 0.5f * x * (1.0f + erff(x * 0.7071067811865476f));
}

template<bool TRANS_B, bool GELU>
__global__ __launch_bounds__(256)
void sgemm_kernel(const float* __restrict__ A, const float* __restrict__ B,
                  const float* __restrict__ bias, float* __restrict__ C,
                  int K, int lda, int ldb, int ldc,
                  long sA1, long sA2, long sB1, long sB2, long sC1, long sC2,
                  int nb2, float alpha)
{
    const int z  = blockIdx.z;
    const int z1 = z / nb2, z2 = z - z1 * nb2;
    A += (long)z1 * sA1 + (long)z2 * sA2;
    B += (long)z1 * sB1 + (long)z2 * sB2;
    C += (long)z1 * sC1 + (long)z2 * sC2;

    __shared__ float As[BK][BM];
    __shared__ float Bs[BK][BN];

    const int tid  = threadIdx.x;
    const int ty   = tid >> 4;           // 0..15
    const int tx   = tid & 15;           // 0..15
    const int row0 = blockIdx.y * BM;
    const int col0 = blockIdx.x * BN;

    // loader indices
    const int a_row = tid >> 2;          // 0..63
    const int a_col = (tid & 3) << 2;    // 0,4,8,12
    const int b_row = tid >> 5;          // 0..7
    const int b_col = (tid & 31) << 2;   // 0..124

    float acc[8][8];
#pragma unroll
    for (int i = 0; i < 8; i++)
#pragma unroll
        for (int j = 0; j < 8; j++) acc[i][j] = 0.f;

    for (int k0 = 0; k0 < K; k0 += BK) {
        // A tile -> As[k][m] (transposed store)
#pragma unroll
        for (int r = 0; r < 2; r++) {
            int m = a_row + r * 64;
            float4 v = *(const float4*)(A + (long)(row0 + m) * lda + (k0 + a_col));
            As[a_col + 0][m] = v.x; As[a_col + 1][m] = v.y;
            As[a_col + 2][m] = v.z; As[a_col + 3][m] = v.w;
        }
        if (!TRANS_B) {
#pragma unroll
            for (int r = 0; r < 2; r++) {
                int kk = b_row + r * 8;
                float4 v = *(const float4*)(B + (long)(k0 + kk) * ldb + (col0 + b_col));
                *(float4*)&Bs[kk][b_col] = v;
            }
        } else {
#pragma unroll
            for (int r = 0; r < 2; r++) {
                int n = a_row + r * 64;
                float4 v = *(const float4*)(B + (long)(col0 + n) * ldb + (k0 + a_col));
                Bs[a_col + 0][n] = v.x; Bs[a_col + 1][n] = v.y;
                Bs[a_col + 2][n] = v.z; Bs[a_col + 3][n] = v.w;
            }
        }
        __syncthreads();

#pragma unroll
        for (int kk = 0; kk < BK; kk++) {
            float a[8], b[8];
#pragma unroll
            for (int i = 0; i < 8; i++) a[i] = As[kk][ty * 8 + i];
#pragma unroll
            for (int j = 0; j < 8; j++) b[j] = Bs[kk][tx * 8 + j];
#pragma unroll
            for (int i = 0; i < 8; i++)
#pragma unroll
                for (int j = 0; j < 8; j++)
                    acc[i][j] = fmaf(a[i], b[j], acc[i][j]);
        }
        __syncthreads();
    }

    // epilogue
#pragma unroll
    for (int i = 0; i < 8; i++) {
        int m = row0 + ty * 8 + i;
#pragma unroll
        for (int j = 0; j < 8; j += 4) {
            int n = col0 + tx * 8 + j;
            float4 v;
            float bx = bias ? bias[n + 0] : 0.f;
            float by = bias ? bias[n + 1] : 0.f;
            float bz = bias ? bias[n + 2] : 0.f;
            float bw = bias ? bias[n + 3] : 0.f;
            v.x = fmaf(acc[i][j + 0], alpha, bx);
            v.y = fmaf(acc[i][j + 1], alpha, by);
            v.z = fmaf(acc[i][j + 2], alpha, bz);
            v.w = fmaf(acc[i][j + 3], alpha, bw);
            if (GELU) {
                v.x = gelu_exact(v.x); v.y = gelu_exact(v.y);
                v.z = gelu_exact(v.z); v.w = gelu_exact(v.w);
            }
            *(float4*)(C + (long)m * ldc + n) = v;
        }
    }
}

// ---------------- patchify + pos-emb ----------------
__global__ void patch_embed_kernel(const float* __restrict__ X,
                                   const float* __restrict__ pos,
                                   float* __restrict__ P)
{
    int i = blockIdx.x * blockDim.x + threadIdx.x;     // over ROWS*D1
    if (i >= ROWS * D1) return;
    int b   = i >> 16;            // /65536
    int rem = i & 65535;
    int n   = rem >> 8;
    int d   = rem & 255;
    int gy = n >> 4, gx = n & 15;
    int py = d >> 4, px = d & 15;
    int y = gy * 16 + py, x = gx * 16 + px;
    P[i] = X[((long)(b * 256 + y)) * 256 + x] + pos[n * 256 + d];
}

// ---------------- softmax over rows of 256 (warp per row) ----------------
__global__ void softmax_kernel(float* __restrict__ A, int nrows)
{
    int row  = blockIdx.x * (blockDim.x >> 5) + (threadIdx.x >> 5);
    if (row >= nrows) return;
    int lane = threadIdx.x & 31;
    float* p = A + (long)row * 256;
    float v[8];
    float mx = -INFINITY;
#pragma unroll
    for (int i = 0; i < 8; i++) { v[i] = p[lane + i * 32]; mx = fmaxf(mx, v[i]); }
#pragma unroll
    for (int o = 16; o > 0; o >>= 1) mx = fmaxf(mx, __shfl_xor_sync(0xffffffffu, mx, o));
    float s = 0.f;
#pragma unroll
    for (int i = 0; i < 8; i++) { v[i] = __expf(v[i] - mx); s += v[i]; }
#pragma unroll
    for (int o = 16; o > 0; o >>= 1) s += __shfl_xor_sync(0xffffffffu, s, o);
    float r = 1.f / s;
#pragma unroll
    for (int i = 0; i < 8; i++) p[lane + i * 32] = v[i] * r;
}

// ---------------- residual add + LayerNorm (warp per row of 256) ----------------
__global__ void add_ln_kernel(float* __restrict__ enc, const float* __restrict__ res,
                              const float* __restrict__ g, const float* __restrict__ bta)
{
    int row  = blockIdx.x * (blockDim.x >> 5) + (threadIdx.x >> 5);
    if (row >= ROWS) return;
    int lane = threadIdx.x & 31;
    float* pe = enc + (long)row * 256;
    const float* pr = res + (long)row * 256;
    float v[8];
    float s = 0.f;
#pragma unroll
    for (int i = 0; i < 8; i++) { v[i] = pe[lane + i * 32] + pr[lane + i * 32]; s += v[i]; }
#pragma unroll
    for (int o = 16; o > 0; o >>= 1) s += __shfl_xor_sync(0xffffffffu, s, o);
    float mu = s * (1.f / 256.f);
    float q = 0.f;
#pragma unroll
    for (int i = 0; i < 8; i++) { float d = v[i] - mu; q += d * d; }
#pragma unroll
    for (int o = 16; o > 0; o >>= 1) q += __shfl_xor_sync(0xffffffffu, q, o);
    float inv = rsqrtf(q * (1.f / 256.f) + LN_EPS);
#pragma unroll
    for (int i = 0; i < 8; i++) {
        int d = lane + i * 32;
        pe[d] = (v[i] - mu) * inv * g[d] + bta[d];
    }
}

// ---------------- final resample: unpatch(16) -> patchify(8) ----------------
__global__ void resample_kernel(const float* __restrict__ enc, float* __restrict__ out)
{
    int i = blockIdx.x * blockDim.x + threadIdx.x;     // over 32*1024*64
    if (i >= Bb * 1024 * 64) return;
    int b   = i >> 16;            // /65536
    int rem = i & 65535;
    int n2  = rem >> 6;
    int d2  = rem & 63;
    int gy2 = n2 >> 5, gx2 = n2 & 31;
    int py2 = d2 >> 3, px2 = d2 & 7;
    int y = gy2 * 8 + py2, x = gx2 * 8 + px2;
    int n1 = (y >> 4) * 16 + (x >> 4);
    int d1 = (y & 15) * 16 + (x & 15);
    out[i] = enc[((long)(b * 256 + n1)) * 256 + d1];
}

// ---------------- host-side launch helpers ----------------
static inline void launch_gemm(const float* A, const float* B, const float* bias, float* C,
                               int M, int N, int K, int lda, int ldb, int ldc,
                               long sA1, long sA2, long sB1, long sB2, long sC1, long sC2,
                               int nb1, int nb2, float alpha, bool transB, bool gelu)
{
    dim3 grid(N / BN, M / BM, nb1 * nb2), block(256);
    if (transB)
        sgemm_kernel<true, false><<<grid, block>>>(A, B, bias, C, K, lda, ldb, ldc,
                                                   sA1, sA2, sB1, sB2, sC1, sC2, nb2, alpha);
    else if (gelu)
        sgemm_kernel<false, true><<<grid, block>>>(A, B, bias, C, K, lda, ldb, ldc,
                                                   sA1, sA2, sB1, sB2, sC1, sC2, nb2, alpha);
    else
        sgemm_kernel<false, false><<<grid, block>>>(A, B, bias, C, K, lda, ldb, ldc,
                                                    sA1, sA2, sB1, sB2, sC1, sC2, nb2, alpha);
}

extern "C" void kernel_launch(void* const* d_in, const int* in_sizes, int n_in,
                              void* d_out, int out_size)
{
    (void)in_sizes; (void)n_in; (void)out_size;
    const float* X    = (const float*)d_in[0];
    const float* pos  = (const float*)d_in[1];
    const float* W_in = (const float*)d_in[2];
    const float* b_in = (const float*)d_in[3];
    const float* Wq   = (const float*)d_in[4];
    const float* bq   = (const float*)d_in[5];
    const float* Wk   = (const float*)d_in[6];
    const float* bk   = (const float*)d_in[7];
    const float* Wv   = (const float*)d_in[8];
    const float* bv   = (const float*)d_in[9];
    const float* Wo   = (const float*)d_in[10];
    const float* bo   = (const float*)d_in[11];
    const float* ln1g = (const float*)d_in[12];
    const float* ln1b = (const float*)d_in[13];
    const float* ln2g = (const float*)d_in[14];
    const float* ln2b = (const float*)d_in[15];
    const float* W1   = (const float*)d_in[16];
    const float* b1   = (const float*)d_in[17];
    const float* W2   = (const float*)d_in[18];
    const float* b2   = (const float*)d_in[19];
    float* out = (float*)d_out;

    float *patch, *enc, *q, *k, *v, *attn, *o, *a, *f1;
    cudaGetSymbolAddress((void**)&patch, g_patch);
    cudaGetSymbolAddress((void**)&enc,   g_enc);
    cudaGetSymbolAddress((void**)&q,     g_q);
    cudaGetSymbolAddress((void**)&k,     g_k);
    cudaGetSymbolAddress((void**)&v,     g_v);
    cudaGetSymbolAddress((void**)&attn,  g_attn);
    cudaGetSymbolAddress((void**)&o,     g_o);
    cudaGetSymbolAddress((void**)&a,     g_a);
    cudaGetSymbolAddress((void**)&f1,    g_f1);

    const float scale = 1.0f / 16.0f;   // 1/sqrt(KD=256)

    // patch + pos emb, then input projection
    patch_embed_kernel<<<(ROWS * D1 + 255) / 256, 256>>>(X, pos, patch);
    launch_gemm(patch, W_in, b_in, enc, ROWS, D1, D1, D1, D1, D1,
                0, 0, 0, 0, 0, 0, 1, 1, 1.f, false, false);

    for (int l = 0; l < LAY; l++) {
        const float* Wq_l = Wq + (long)l * D1 * QC;
        const float* Wk_l = Wk + (long)l * D1 * QC;
        const float* Wv_l = Wv + (long)l * D1 * QC;
        const float* bq_l = bq + (long)l * QC;
        const float* bk_l = bk + (long)l * QC;
        const float* bv_l = bv + (long)l * QC;
        const float* Wo_l = Wo + (long)l * QC * D1;
        const float* bo_l = bo + (long)l * D1;
        const float* W1_l = W1 + (long)l * D1 * HID;
        const float* b1_l = b1 + (long)l * HID;
        const float* W2_l = W2 + (long)l * HID * D1;
        const float* b2_l = b2 + (long)l * D1;

        // q,k,v = enc @ W{q,k,v} + b   -> [8192, 2048] laid out [b,n,h,kd]
        launch_gemm(enc, Wq_l, bq_l, q, ROWS, QC, D1, D1, QC, QC,
                    0, 0, 0, 0, 0, 0, 1, 1, 1.f, false, false);
        launch_gemm(enc, Wk_l, bk_l, k, ROWS, QC, D1, D1, QC, QC,
                    0, 0, 0, 0, 0, 0, 1, 1, 1.f, false, false);
        launch_gemm(enc, Wv_l, bv_l, v, ROWS, QC, D1, D1, QC, QC,
                    0, 0, 0, 0, 0, 0, 1, 1, 1.f, false, false);

        // logits[b,h,q,n] = scale * Q_bh @ K_bh^T  (batched NT, 256 batches)
        launch_gemm(q, k, nullptr, attn, N1, N1, KD, QC, QC, N1,
                    (long)N1 * QC, KD,            // A: b, h
                    (long)N1 * QC, KD,            // B: b, h
                    (long)NH * N1 * N1, (long)N1 * N1,  // C: b, h
                    Bb, NH, scale, true, false);

        softmax_kernel<<<(Bb * NH * N1) / 8, 256>>>(attn, Bb * NH * N1);

        // o[b,q,h,kd] = attn @ V_bh  (batched NN)
        launch_gemm(attn, v, nullptr, o, N1, KD, N1, N1, QC, QC,
                    (long)NH * N1 * N1, (long)N1 * N1,  // A: b, h
                    (long)N1 * QC, KD,                  // B: b, h
                    (long)N1 * QC, KD,                  // C: b, h
                    Bb, NH, 1.f, false, false);

        // a = o @ Wo + bo
        launch_gemm(o, Wo_l, bo_l, a, ROWS, D1, QC, QC, D1, D1,
                    0, 0, 0, 0, 0, 0, 1, 1, 1.f, false, false);

        // enc = LN(enc + a)
        add_ln_kernel<<<ROWS / 8, 256>>>(enc, a, ln1g + l * D1, ln1b + l * D1);

        // f1 = gelu(enc @ W1 + b1);  f2 = gelu(f1 @ W2 + b2) (into a)
        launch_gemm(enc, W1_l, b1_l, f1, ROWS, HID, D1, D1, HID, HID,
                    0, 0, 0, 0, 0, 0, 1, 1, 1.f, false, true);
        launch_gemm(f1, W2_l, b2_l, a, ROWS, D1, HID, HID, D1, D1,
                    0, 0, 0, 0, 0, 0, 1, 1, 1.f, false, true);

        // enc = LN(enc + f2)
        add_ln_kernel<<<ROWS / 8, 256>>>(enc, a, ln2g + l * D1, ln2b + l * D1);
    }

    resample_kernel<<<(Bb * 1024 * 64 + 255) / 256, 256>>>(enc, out);
}

// round 4
// speedup vs baseline: 2.2143x; 2.2143x over previous
#include <cuda_runtime.h>
#include <math.h>
#include <stdint.h>

// ---------------- problem constants ----------------
constexpr int Bb   = 32;
constexpr int N1   = 256;
constexpr int D1   = 256;
constexpr int NH   = 8;
constexpr int KD   = 256;
constexpr int HID  = 1024;
constexpr int LAY  = 8;
constexpr int ROWS = Bb * N1;      // 8192
constexpr int QC   = NH * KD;      // 2048
constexpr float LN_EPS = 1e-3f;

// ---------------- scratch (static device memory; no allocation) ----------------
__device__ float g_patch[ROWS * D1];
__device__ float g_enc  [ROWS * D1];
__device__ float g_q    [ROWS * QC];
__device__ float g_k    [ROWS * QC];
__device__ float g_v    [ROWS * QC];
__device__ float g_attn [Bb * NH * N1 * N1];
__device__ float g_o    [ROWS * QC];
__device__ float g_a    [ROWS * D1];
__device__ float g_f1   [ROWS * HID];

// ---------------- helpers ----------------
__device__ __forceinline__ float gelu_exact(float x) {
    return 0.5f * x * (1.0f + erff(x * 0.7071067811865476f));
}

__device__ __forceinline__ uint32_t f2tf32(float x) {
    uint32_t r;
    asm("cvt.rna.tf32.f32 %0, %1;" : "=r"(r) : "f"(x));
    return r;
}

__device__ __forceinline__ void mma_tf32(float c[4], const uint32_t a[4], const uint32_t b[2]) {
    asm volatile(
        "mma.sync.aligned.m16n8k8.row.col.f32.tf32.tf32.f32 "
        "{%0,%1,%2,%3}, {%4,%5,%6,%7}, {%8,%9}, {%0,%1,%2,%3};\n"
        : "+f"(c[0]), "+f"(c[1]), "+f"(c[2]), "+f"(c[3])
        : "r"(a[0]), "r"(a[1]), "r"(a[2]), "r"(a[3]),
          "r"(b[0]), "r"(b[1]));
}

// ---------------- TF32 tensor-core GEMM ----------------
// C[z] = act( alpha * A[z] @ op(B[z]) + bias )
// A: [M,K] row-major.  NN: B [K,N];  NT: B [N,K] (computes A.B^T)
// Block tile 128x128xBK16, 8 warps (2m x 4n), warp tile 64x32, mma m16n8k8.
#define BM 128
#define BN 128
#define BK 16
#define AS_LD 20    // As[m][k], stride 20 floats (80B rows: 16B-aligned, conflict-free frags)
#define BS_LD 136   // Bs[k][n], stride 136 floats (8k+n bank map: conflict-free frags)

template<bool TRANS_B, bool GELU>
__global__ __launch_bounds__(256)
void mma_gemm_kernel(const float* __restrict__ A, const float* __restrict__ B,
                     const float* __restrict__ bias, float* __restrict__ C,
                     int K, int lda, int ldb, int ldc,
                     long sA1, long sA2, long sB1, long sB2, long sC1, long sC2,
                     int nb2, float alpha)
{
    const int z  = blockIdx.z;
    const int z1 = z / nb2, z2 = z - z1 * nb2;
    A += (long)z1 * sA1 + (long)z2 * sA2;
    B += (long)z1 * sB1 + (long)z2 * sB2;
    C += (long)z1 * sC1 + (long)z2 * sC2;

    __shared__ float As[BM][AS_LD];   // tf32 bits, [m][k]
    __shared__ float Bs[BK][BS_LD];   // tf32 bits, [k][n]

    const int tid  = threadIdx.x;
    const int lane = tid & 31;
    const int wid  = tid >> 5;
    const int wm   = wid >> 2;        // 0..1
    const int wn   = wid & 3;         // 0..3
    const int row0 = blockIdx.y * BM;
    const int col0 = blockIdx.x * BN;

    // loader indices
    const int a_row = tid >> 2;          // 0..63
    const int a_col = (tid & 3) << 2;    // 0,4,8,12
    const int b_row = tid >> 5;          // 0..7
    const int b_col = (tid & 31) << 2;   // 0..124

    const int qrow = lane >> 2;          // 0..7
    const int qcol = lane & 3;           // 0..3

    float acc[4][4][4];
#pragma unroll
    for (int t = 0; t < 4; t++)
#pragma unroll
        for (int u = 0; u < 4; u++)
#pragma unroll
            for (int r = 0; r < 4; r++) acc[t][u][r] = 0.f;

    for (int k0 = 0; k0 < K; k0 += BK) {
        // ---- A tile: [BM][BK] -> As[m][k], converted to tf32
#pragma unroll
        for (int r = 0; r < 2; r++) {
            int m = a_row + r * 64;
            float4 v = *(const float4*)(A + (long)(row0 + m) * lda + (k0 + a_col));
            float4 w;
            w.x = __uint_as_float(f2tf32(v.x));
            w.y = __uint_as_float(f2tf32(v.y));
            w.z = __uint_as_float(f2tf32(v.z));
            w.w = __uint_as_float(f2tf32(v.w));
            *(float4*)&As[m][a_col] = w;
        }
        // ---- B tile -> Bs[k][n]
        if (!TRANS_B) {
#pragma unroll
            for (int r = 0; r < 2; r++) {
                int kk = b_row + r * 8;
                float4 v = *(const float4*)(B + (long)(k0 + kk) * ldb + (col0 + b_col));
                float4 w;
                w.x = __uint_as_float(f2tf32(v.x));
                w.y = __uint_as_float(f2tf32(v.y));
                w.z = __uint_as_float(f2tf32(v.z));
                w.w = __uint_as_float(f2tf32(v.w));
                *(float4*)&Bs[kk][b_col] = w;
            }
        } else {
#pragma unroll
            for (int r = 0; r < 2; r++) {
                int n = a_row + r * 64;
                float4 v = *(const float4*)(B + (long)(col0 + n) * ldb + (k0 + a_col));
                Bs[a_col + 0][n] = __uint_as_float(f2tf32(v.x));
                Bs[a_col + 1][n] = __uint_as_float(f2tf32(v.y));
                Bs[a_col + 2][n] = __uint_as_float(f2tf32(v.z));
                Bs[a_col + 3][n] = __uint_as_float(f2tf32(v.w));
            }
        }
        __syncthreads();

#pragma unroll
        for (int ks = 0; ks < BK; ks += 8) {
            uint32_t afrag[4][4];
#pragma unroll
            for (int t = 0; t < 4; t++) {
                int mb = wm * 64 + t * 16;
                afrag[t][0] = __float_as_uint(As[mb + qrow    ][ks + qcol    ]);
                afrag[t][1] = __float_as_uint(As[mb + qrow + 8][ks + qcol    ]);
                afrag[t][2] = __float_as_uint(As[mb + qrow    ][ks + qcol + 4]);
                afrag[t][3] = __float_as_uint(As[mb + qrow + 8][ks + qcol + 4]);
            }
            uint32_t bfrag[4][2];
#pragma unroll
            for (int u = 0; u < 4; u++) {
                int nb = wn * 32 + u * 8;
                bfrag[u][0] = __float_as_uint(Bs[ks + qcol    ][nb + qrow]);
                bfrag[u][1] = __float_as_uint(Bs[ks + qcol + 4][nb + qrow]);
            }
#pragma unroll
            for (int t = 0; t < 4; t++)
#pragma unroll
                for (int u = 0; u < 4; u++)
                    mma_tf32(acc[t][u], afrag[t], bfrag[u]);
        }
        __syncthreads();
    }

    // ---- epilogue: alpha, bias, gelu; float2 stores
#pragma unroll
    for (int t = 0; t < 4; t++) {
        int r0 = row0 + wm * 64 + t * 16 + qrow;
#pragma unroll
        for (int u = 0; u < 4; u++) {
            int n = col0 + wn * 32 + u * 8 + qcol * 2;
            float bx = bias ? bias[n + 0] : 0.f;
            float by = bias ? bias[n + 1] : 0.f;
            float2 v0, v1;
            v0.x = fmaf(acc[t][u][0], alpha, bx);
            v0.y = fmaf(acc[t][u][1], alpha, by);
            v1.x = fmaf(acc[t][u][2], alpha, bx);
            v1.y = fmaf(acc[t][u][3], alpha, by);
            if (GELU) {
                v0.x = gelu_exact(v0.x); v0.y = gelu_exact(v0.y);
                v1.x = gelu_exact(v1.x); v1.y = gelu_exact(v1.y);
            }
            *(float2*)(C + (long)r0 * ldc + n)       = v0;
            *(float2*)(C + (long)(r0 + 8) * ldc + n) = v1;
        }
    }
}

// ---------------- patchify + pos-emb ----------------
__global__ void patch_embed_kernel(const float* __restrict__ X,
                                   const float* __restrict__ pos,
                                   float* __restrict__ P)
{
    int i = blockIdx.x * blockDim.x + threadIdx.x;
    if (i >= ROWS * D1) return;
    int b   = i >> 16;
    int rem = i & 65535;
    int n   = rem >> 8;
    int d   = rem & 255;
    int gy = n >> 4, gx = n & 15;
    int py = d >> 4, px = d & 15;
    int y = gy * 16 + py, x = gx * 16 + px;
    P[i] = X[((long)(b * 256 + y)) * 256 + x] + pos[n * 256 + d];
}

// ---------------- softmax over rows of 256 (warp per row) ----------------
__global__ void softmax_kernel(float* __restrict__ A, int nrows)
{
    int row  = blockIdx.x * (blockDim.x >> 5) + (threadIdx.x >> 5);
    if (row >= nrows) return;
    int lane = threadIdx.x & 31;
    float* p = A + (long)row * 256;
    float v[8];
    float mx = -INFINITY;
#pragma unroll
    for (int i = 0; i < 8; i++) { v[i] = p[lane + i * 32]; mx = fmaxf(mx, v[i]); }
#pragma unroll
    for (int o = 16; o > 0; o >>= 1) mx = fmaxf(mx, __shfl_xor_sync(0xffffffffu, mx, o));
    float s = 0.f;
#pragma unroll
    for (int i = 0; i < 8; i++) { v[i] = __expf(v[i] - mx); s += v[i]; }
#pragma unroll
    for (int o = 16; o > 0; o >>= 1) s += __shfl_xor_sync(0xffffffffu, s, o);
    float r = 1.f / s;
#pragma unroll
    for (int i = 0; i < 8; i++) p[lane + i * 32] = v[i] * r;
}

// ---------------- residual add + LayerNorm (warp per row of 256) ----------------
__global__ void add_ln_kernel(float* __restrict__ enc, const float* __restrict__ res,
                              const float* __restrict__ g, const float* __restrict__ bta)
{
    int row  = blockIdx.x * (blockDim.x >> 5) + (threadIdx.x >> 5);
    if (row >= ROWS) return;
    int lane = threadIdx.x & 31;
    float* pe = enc + (long)row * 256;
    const float* pr = res + (long)row * 256;
    float v[8];
    float s = 0.f;
#pragma unroll
    for (int i = 0; i < 8; i++) { v[i] = pe[lane + i * 32] + pr[lane + i * 32]; s += v[i]; }
#pragma unroll
    for (int o = 16; o > 0; o >>= 1) s += __shfl_xor_sync(0xffffffffu, s, o);
    float mu = s * (1.f / 256.f);
    float q = 0.f;
#pragma unroll
    for (int i = 0; i < 8; i++) { float d = v[i] - mu; q += d * d; }
#pragma unroll
    for (int o = 16; o > 0; o >>= 1) q += __shfl_xor_sync(0xffffffffu, q, o);
    float inv = rsqrtf(q * (1.f / 256.f) + LN_EPS);
#pragma unroll
    for (int i = 0; i < 8; i++) {
        int d = lane + i * 32;
        pe[d] = (v[i] - mu) * inv * g[d] + bta[d];
    }
}

// ---------------- final resample: unpatch(16) -> patchify(8) ----------------
__global__ void resample_kernel(const float* __restrict__ enc, float* __restrict__ out)
{
    int i = blockIdx.x * blockDim.x + threadIdx.x;
    if (i >= Bb * 1024 * 64) return;
    int b   = i >> 16;
    int rem = i & 65535;
    int n2  = rem >> 6;
    int d2  = rem & 63;
    int gy2 = n2 >> 5, gx2 = n2 & 31;
    int py2 = d2 >> 3, px2 = d2 & 7;
    int y = gy2 * 8 + py2, x = gx2 * 8 + px2;
    int n1 = (y >> 4) * 16 + (x >> 4);
    int d1 = (y & 15) * 16 + (x & 15);
    out[i] = enc[((long)(b * 256 + n1)) * 256 + d1];
}

// ---------------- host-side launch helper ----------------
static inline void launch_gemm(const float* A, const float* B, const float* bias, float* C,
                               int M, int N, int K, int lda, int ldb, int ldc,
                               long sA1, long sA2, long sB1, long sB2, long sC1, long sC2,
                               int nb1, int nb2, float alpha, bool transB, bool gelu)
{
    dim3 grid(N / BN, M / BM, nb1 * nb2), block(256);
    if (transB)
        mma_gemm_kernel<true, false><<<grid, block>>>(A, B, bias, C, K, lda, ldb, ldc,
                                                      sA1, sA2, sB1, sB2, sC1, sC2, nb2, alpha);
    else if (gelu)
        mma_gemm_kernel<false, true><<<grid, block>>>(A, B, bias, C, K, lda, ldb, ldc,
                                                      sA1, sA2, sB1, sB2, sC1, sC2, nb2, alpha);
    else
        mma_gemm_kernel<false, false><<<grid, block>>>(A, B, bias, C, K, lda, ldb, ldc,
                                                       sA1, sA2, sB1, sB2, sC1, sC2, nb2, alpha);
}

extern "C" void kernel_launch(void* const* d_in, const int* in_sizes, int n_in,
                              void* d_out, int out_size)
{
    (void)in_sizes; (void)n_in; (void)out_size;
    const float* X    = (const float*)d_in[0];
    const float* pos  = (const float*)d_in[1];
    const float* W_in = (const float*)d_in[2];
    const float* b_in = (const float*)d_in[3];
    const float* Wq   = (const float*)d_in[4];
    const float* bq   = (const float*)d_in[5];
    const float* Wk   = (const float*)d_in[6];
    const float* bk   = (const float*)d_in[7];
    const float* Wv   = (const float*)d_in[8];
    const float* bv   = (const float*)d_in[9];
    const float* Wo   = (const float*)d_in[10];
    const float* bo   = (const float*)d_in[11];
    const float* ln1g = (const float*)d_in[12];
    const float* ln1b = (const float*)d_in[13];
    const float* ln2g = (const float*)d_in[14];
    const float* ln2b = (const float*)d_in[15];
    const float* W1   = (const float*)d_in[16];
    const float* b1   = (const float*)d_in[17];
    const float* W2   = (const float*)d_in[18];
    const float* b2   = (const float*)d_in[19];
    float* out = (float*)d_out;

    float *patch, *enc, *q, *k, *v, *attn, *o, *a, *f1;
    cudaGetSymbolAddress((void**)&patch, g_patch);
    cudaGetSymbolAddress((void**)&enc,   g_enc);
    cudaGetSymbolAddress((void**)&q,     g_q);
    cudaGetSymbolAddress((void**)&k,     g_k);
    cudaGetSymbolAddress((void**)&v,     g_v);
    cudaGetSymbolAddress((void**)&attn,  g_attn);
    cudaGetSymbolAddress((void**)&o,     g_o);
    cudaGetSymbolAddress((void**)&a,     g_a);
    cudaGetSymbolAddress((void**)&f1,    g_f1);

    const float scale = 1.0f / 16.0f;   // 1/sqrt(KD=256)

    patch_embed_kernel<<<(ROWS * D1 + 255) / 256, 256>>>(X, pos, patch);
    launch_gemm(patch, W_in, b_in, enc, ROWS, D1, D1, D1, D1, D1,
                0, 0, 0, 0, 0, 0, 1, 1, 1.f, false, false);

    for (int l = 0; l < LAY; l++) {
        const float* Wq_l = Wq + (long)l * D1 * QC;
        const float* Wk_l = Wk + (long)l * D1 * QC;
        const float* Wv_l = Wv + (long)l * D1 * QC;
        const float* bq_l = bq + (long)l * QC;
        const float* bk_l = bk + (long)l * QC;
        const float* bv_l = bv + (long)l * QC;
        const float* Wo_l = Wo + (long)l * QC * D1;
        const float* bo_l = bo + (long)l * D1;
        const float* W1_l = W1 + (long)l * D1 * HID;
        const float* b1_l = b1 + (long)l * HID;
        const float* W2_l = W2 + (long)l * HID * D1;
        const float* b2_l = b2 + (long)l * D1;

        launch_gemm(enc, Wq_l, bq_l, q, ROWS, QC, D1, D1, QC, QC,
                    0, 0, 0, 0, 0, 0, 1, 1, 1.f, false, false);
        launch_gemm(enc, Wk_l, bk_l, k, ROWS, QC, D1, D1, QC, QC,
                    0, 0, 0, 0, 0, 0, 1, 1, 1.f, false, false);
        launch_gemm(enc, Wv_l, bv_l, v, ROWS, QC, D1, D1, QC, QC,
                    0, 0, 0, 0, 0, 0, 1, 1, 1.f, false, false);

        // logits[b,h,q,n] = scale * Q_bh @ K_bh^T
        launch_gemm(q, k, nullptr, attn, N1, N1, KD, QC, QC, N1,
                    (long)N1 * QC, KD,
                    (long)N1 * QC, KD,
                    (long)NH * N1 * N1, (long)N1 * N1,
                    Bb, NH, scale, true, false);

        softmax_kernel<<<(Bb * NH * N1) / 8, 256>>>(attn, Bb * NH * N1);

        // o[b,q,h,kd] = attn @ V_bh
        launch_gemm(attn, v, nullptr, o, N1, KD, N1, N1, QC, QC,
                    (long)NH * N1 * N1, (long)N1 * N1,
                    (long)N1 * QC, KD,
                    (long)N1 * QC, KD,
                    Bb, NH, 1.f, false, false);

        launch_gemm(o, Wo_l, bo_l, a, ROWS, D1, QC, QC, D1, D1,
                    0, 0, 0, 0, 0, 0, 1, 1, 1.f, false, false);

        add_ln_kernel<<<ROWS / 8, 256>>>(enc, a, ln1g + l * D1, ln1b + l * D1);

        launch_gemm(enc, W1_l, b1_l, f1, ROWS, HID, D1, D1, HID, HID,
                    0, 0, 0, 0, 0, 0, 1, 1, 1.f, false, true);
        launch_gemm(f1, W2_l, b2_l, a, ROWS, D1, HID, HID, D1, D1,
                    0, 0, 0, 0, 0, 0, 1, 1, 1.f, false, true);

        add_ln_kernel<<<ROWS / 8, 256>>>(enc, a, ln2g + l * D1, ln2b + l * D1);
    }

    resample_kernel<<<(Bb * 1024 * 64 + 255) / 256, 256>>>(enc, out);
}

// round 8
// speedup vs baseline: 2.8796x; 1.3005x over previous
#include <cuda_runtime.h>
#include <math.h>
#include <stdint.h>

// ---------------- problem constants ----------------
constexpr int Bb   = 32;
constexpr int N1   = 256;
constexpr int D1   = 256;
constexpr int NH   = 8;
constexpr int KD   = 256;
constexpr int HID  = 1024;
constexpr int LAY  = 8;
constexpr int ROWS = Bb * N1;      // 8192
constexpr int QC   = NH * KD;      // 2048
constexpr float LN_EPS = 1e-3f;

// ---------------- scratch (static device memory; no allocation) ----------------
__device__ float g_patch[ROWS * D1];
__device__ float g_enc  [ROWS * D1];
__device__ float g_q    [ROWS * QC];
__device__ float g_k    [ROWS * QC];
__device__ float g_v    [ROWS * QC];
__device__ float g_attn [Bb * NH * N1 * N1];
__device__ float g_o    [ROWS * QC];
__device__ float g_a    [ROWS * D1];
__device__ float g_f1   [ROWS * HID];

// ---------------- helpers ----------------
__device__ __forceinline__ float gelu_exact(float x) {
    return 0.5f * x * (1.0f + erff(x * 0.7071067811865476f));
}
__device__ __forceinline__ uint32_t f2tf32(float x) {
    uint32_t r;
    asm("cvt.rna.tf32.f32 %0, %1;" : "=r"(r) : "f"(x));
    return r;
}
__device__ __forceinline__ void mma_tf32(float c[4], const uint32_t a[4], const uint32_t b[2]) {
    asm volatile(
        "mma.sync.aligned.m16n8k8.row.col.f32.tf32.tf32.f32 "
        "{%0,%1,%2,%3}, {%4,%5,%6,%7}, {%8,%9}, {%0,%1,%2,%3};\n"
        : "+f"(c[0]), "+f"(c[1]), "+f"(c[2]), "+f"(c[3])
        : "r"(a[0]), "r"(a[1]), "r"(a[2]), "r"(a[3]),
          "r"(b[0]), "r"(b[1]));
}
__device__ __forceinline__ void cp_async16(uint32_t dst_smem, const void* src) {
    asm volatile("cp.async.cg.shared.global [%0], [%1], 16;" :: "r"(dst_smem), "l"(src));
}
__device__ __forceinline__ void cp_commit() {
    asm volatile("cp.async.commit_group;" ::: "memory");
}
template<int N>
__device__ __forceinline__ void cp_wait() {
    asm volatile("cp.async.wait_group %0;" :: "n"(N) : "memory");
}

// ---------------- TF32 tensor-core GEMM, cp.async double-buffered ----------------
// C[z] = act( alpha * A[z] @ op(B[z]) + bias )
// A: [M,K] row-major.  NN: B [K,N];  NT: B [N,K] (computes A.B^T)
// Block tile 128x128xBK16, 8 warps (2m x 4n), warp tile 64x32, mma m16n8k8.
#define BM 128
#define BN 128
#define BK 16
#define AS_LD 20    // As[m][k] stride 20 floats: conflict-free frag loads, 16B-aligned rows
#define BS_LD 136   // Bs[k][n] stride 136 floats (NN): conflict-free frag loads
#define STG_F 2560  // floats per stage buffer (max of 128*20, 16*136, 128*20)

template<bool TRANS_B, bool GELU>
__global__ __launch_bounds__(256, 2)
void mma_gemm_kernel(const float* __restrict__ A, const float* __restrict__ B,
                     const float* __restrict__ bias, float* __restrict__ C,
                     int K, int lda, int ldb, int ldc,
                     long sA1, long sA2, long sB1, long sB2, long sC1, long sC2,
                     int nb2, float alpha)
{
    const int z  = blockIdx.z;
    const int z1 = z / nb2, z2 = z - z1 * nb2;
    A += (long)z1 * sA1 + (long)z2 * sA2;
    B += (long)z1 * sB1 + (long)z2 * sB2;
    C += (long)z1 * sC1 + (long)z2 * sC2;

    __shared__ alignas(16) float As[2][STG_F];   // raw fp32, [m][k] stride AS_LD
    __shared__ alignas(16) float Bs[2][STG_F];   // NN: [k][n] stride BS_LD; NT: [n][k] stride AS_LD

    const int tid  = threadIdx.x;
    const int lane = tid & 31;
    const int wid  = tid >> 5;
    const int wm   = wid >> 2;           // 0..1
    const int wn   = wid & 3;            // 0..3
    const int row0 = blockIdx.y * BM;
    const int col0 = blockIdx.x * BN;

    const int a_row = tid >> 2;          // 0..63
    const int a_col = (tid & 3) << 2;    // 0,4,8,12
    const int b_row = tid >> 5;          // 0..7
    const int b_col = (tid & 31) << 2;   // 0..124

    const int qrow = lane >> 2;          // 0..7
    const int qcol = lane & 3;           // 0..3

    const uint32_t sAs = (uint32_t)__cvta_generic_to_shared(&As[0][0]);
    const uint32_t sBs = (uint32_t)__cvta_generic_to_shared(&Bs[0][0]);

    float acc[4][4][4];
#pragma unroll
    for (int t = 0; t < 4; t++)
#pragma unroll
        for (int u = 0; u < 4; u++)
#pragma unroll
            for (int r = 0; r < 4; r++) acc[t][u][r] = 0.f;

    const int steps = K >> 4;            // K is a multiple of 32 everywhere here

    // stage-fill via cp.async (4x 16B per thread per stage)
    auto fill = [&](int buf, int k0) {
#pragma unroll
        for (int r = 0; r < 2; r++) {
            int m = a_row + r * 64;
            cp_async16(sAs + (uint32_t)(buf * STG_F + m * AS_LD + a_col) * 4,
                       A + (long)(row0 + m) * lda + k0 + a_col);
        }
        if (!TRANS_B) {
#pragma unroll
            for (int r = 0; r < 2; r++) {
                int kk = b_row + r * 8;
                cp_async16(sBs + (uint32_t)(buf * STG_F + kk * BS_LD + b_col) * 4,
                           B + (long)(k0 + kk) * ldb + col0 + b_col);
            }
        } else {
#pragma unroll
            for (int r = 0; r < 2; r++) {
                int n = a_row + r * 64;
                cp_async16(sBs + (uint32_t)(buf * STG_F + n * AS_LD + a_col) * 4,
                           B + (long)(col0 + n) * ldb + k0 + a_col);
            }
        }
    };

    fill(0, 0);        cp_commit();
    fill(1, BK);       cp_commit();

    for (int s = 0; s < steps; s++) {
        if (s + 1 < steps) cp_wait<1>(); else cp_wait<0>();
        __syncthreads();
        const float* Ab = As[s & 1];
        const float* Bbuf = Bs[s & 1];

#pragma unroll
        for (int ks = 0; ks < BK; ks += 8) {
            uint32_t afrag[4][4];
#pragma unroll
            for (int t = 0; t < 4; t++) {
                int mb = wm * 64 + t * 16;
                afrag[t][0] = f2tf32(Ab[(mb + qrow)     * AS_LD + ks + qcol    ]);
                afrag[t][1] = f2tf32(Ab[(mb + qrow + 8) * AS_LD + ks + qcol    ]);
                afrag[t][2] = f2tf32(Ab[(mb + qrow)     * AS_LD + ks + qcol + 4]);
                afrag[t][3] = f2tf32(Ab[(mb + qrow + 8) * AS_LD + ks + qcol + 4]);
            }
            uint32_t bfrag[4][2];
#pragma unroll
            for (int u = 0; u < 4; u++) {
                int nb = wn * 32 + u * 8;
                if (!TRANS_B) {
                    bfrag[u][0] = f2tf32(Bbuf[(ks + qcol)     * BS_LD + nb + qrow]);
                    bfrag[u][1] = f2tf32(Bbuf[(ks + qcol + 4) * BS_LD + nb + qrow]);
                } else {
                    bfrag[u][0] = f2tf32(Bbuf[(nb + qrow) * AS_LD + ks + qcol    ]);
                    bfrag[u][1] = f2tf32(Bbuf[(nb + qrow) * AS_LD + ks + qcol + 4]);
                }
            }
#pragma unroll
            for (int t = 0; t < 4; t++)
#pragma unroll
                for (int u = 0; u < 4; u++)
                    mma_tf32(acc[t][u], afrag[t], bfrag[u]);
        }
        __syncthreads();
        if (s + 2 < steps) { fill(s & 1, (s + 2) << 4); cp_commit(); }
    }

    // ---- epilogue: alpha, bias, gelu; float2 stores ----
#pragma unroll
    for (int t = 0; t < 4; t++) {
        int r0 = row0 + wm * 64 + t * 16 + qrow;
#pragma unroll
        for (int u = 0; u < 4; u++) {
            int n = col0 + wn * 32 + u * 8 + qcol * 2;
            float bx = bias ? bias[n + 0] : 0.f;
            float by = bias ? bias[n + 1] : 0.f;
            float2 v0, v1;
            v0.x = fmaf(acc[t][u][0], alpha, bx);
            v0.y = fmaf(acc[t][u][1], alpha, by);
            v1.x = fmaf(acc[t][u][2], alpha, bx);
            v1.y = fmaf(acc[t][u][3], alpha, by);
            if (GELU) {
                v0.x = gelu_exact(v0.x); v0.y = gelu_exact(v0.y);
                v1.x = gelu_exact(v1.x); v1.y = gelu_exact(v1.y);
            }
            *(float2*)(C + (long)r0 * ldc + n)       = v0;
            *(float2*)(C + (long)(r0 + 8) * ldc + n) = v1;
        }
    }
}

// ---------------- patchify + pos-emb ----------------
__global__ void patch_embed_kernel(const float* __restrict__ X,
                                   const float* __restrict__ pos,
                                   float* __restrict__ P)
{
    int i = blockIdx.x * blockDim.x + threadIdx.x;
    if (i >= ROWS * D1) return;
    int b   = i >> 16;
    int rem = i & 65535;
    int n   = rem >> 8;
    int d   = rem & 255;
    int gy = n >> 4, gx = n & 15;
    int py = d >> 4, px = d & 15;
    int y = gy * 16 + py, x = gx * 16 + px;
    P[i] = X[((long)(b * 256 + y)) * 256 + x] + pos[n * 256 + d];
}

// ---------------- softmax over rows of 256 (warp per row) ----------------
__global__ void softmax_kernel(float* __restrict__ A, int nrows)
{
    int row  = blockIdx.x * (blockDim.x >> 5) + (threadIdx.x >> 5);
    if (row >= nrows) return;
    int lane = threadIdx.x & 31;
    float* p = A + (long)row * 256;
    float v[8];
    float mx = -INFINITY;
#pragma unroll
    for (int i = 0; i < 8; i++) { v[i] = p[lane + i * 32]; mx = fmaxf(mx, v[i]); }
#pragma unroll
    for (int o = 16; o > 0; o >>= 1) mx = fmaxf(mx, __shfl_xor_sync(0xffffffffu, mx, o));
    float s = 0.f;
#pragma unroll
    for (int i = 0; i < 8; i++) { v[i] = __expf(v[i] - mx); s += v[i]; }
#pragma unroll
    for (int o = 16; o > 0; o >>= 1) s += __shfl_xor_sync(0xffffffffu, s, o);
    float r = 1.f / s;
#pragma unroll
    for (int i = 0; i < 8; i++) p[lane + i * 32] = v[i] * r;
}

// ---------------- residual add + LayerNorm (warp per row of 256) ----------------
__global__ void add_ln_kernel(float* __restrict__ enc, const float* __restrict__ res,
                              const float* __restrict__ g, const float* __restrict__ bta)
{
    int row  = blockIdx.x * (blockDim.x >> 5) + (threadIdx.x >> 5);
    if (row >= ROWS) return;
    int lane = threadIdx.x & 31;
    float* pe = enc + (long)row * 256;
    const float* pr = res + (long)row * 256;
    float v[8];
    float s = 0.f;
#pragma unroll
    for (int i = 0; i < 8; i++) { v[i] = pe[lane + i * 32] + pr[lane + i * 32]; s += v[i]; }
#pragma unroll
    for (int o = 16; o > 0; o >>= 1) s += __shfl_xor_sync(0xffffffffu, s, o);
    float mu = s * (1.f / 256.f);
    float q = 0.f;
#pragma unroll
    for (int i = 0; i < 8; i++) { float d = v[i] - mu; q += d * d; }
#pragma unroll
    for (int o = 16; o > 0; o >>= 1) q += __shfl_xor_sync(0xffffffffu, q, o);
    float inv = rsqrtf(q * (1.f / 256.f) + LN_EPS);
#pragma unroll
    for (int i = 0; i < 8; i++) {
        int d = lane + i * 32;
        pe[d] = (v[i] - mu) * inv * g[d] + bta[d];
    }
}

// ---------------- final resample: unpatch(16) -> patchify(8) ----------------
__global__ void resample_kernel(const float* __restrict__ enc, float* __restrict__ out)
{
    int i = blockIdx.x * blockDim.x + threadIdx.x;
    if (i >= Bb * 1024 * 64) return;
    int b   = i >> 16;
    int rem = i & 65535;
    int n2  = rem >> 6;
    int d2  = rem & 63;
    int gy2 = n2 >> 5, gx2 = n2 & 31;
    int py2 = d2 >> 3, px2 = d2 & 7;
    int y = gy2 * 8 + py2, x = gx2 * 8 + px2;
    int n1 = (y >> 4) * 16 + (x >> 4);
    int d1 = (y & 15) * 16 + (x & 15);
    out[i] = enc[((long)(b * 256 + n1)) * 256 + d1];
}

// ---------------- host-side launch helper ----------------
static inline void launch_gemm(const float* A, const float* B, const float* bias, float* C,
                               int M, int N, int K, int lda, int ldb, int ldc,
                               long sA1, long sA2, long sB1, long sB2, long sC1, long sC2,
                               int nb1, int nb2, float alpha, bool transB, bool gelu)
{
    dim3 grid(N / BN, M / BM, nb1 * nb2), block(256);
    if (transB)
        mma_gemm_kernel<true, false><<<grid, block>>>(A, B, bias, C, K, lda, ldb, ldc,
                                                      sA1, sA2, sB1, sB2, sC1, sC2, nb2, alpha);
    else if (gelu)
        mma_gemm_kernel<false, true><<<grid, block>>>(A, B, bias, C, K, lda, ldb, ldc,
                                                      sA1, sA2, sB1, sB2, sC1, sC2, nb2, alpha);
    else
        mma_gemm_kernel<false, false><<<grid, block>>>(A, B, bias, C, K, lda, ldb, ldc,
                                                       sA1, sA2, sB1, sB2, sC1, sC2, nb2, alpha);
}

extern "C" void kernel_launch(void* const* d_in, const int* in_sizes, int n_in,
                              void* d_out, int out_size)
{
    (void)in_sizes; (void)n_in; (void)out_size;
    const float* X    = (const float*)d_in[0];
    const float* pos  = (const float*)d_in[1];
    const float* W_in = (const float*)d_in[2];
    const float* b_in = (const float*)d_in[3];
    const float* Wq   = (const float*)d_in[4];
    const float* bq   = (const float*)d_in[5];
    const float* Wk   = (const float*)d_in[6];
    const float* bk   = (const float*)d_in[7];
    const float* Wv   = (const float*)d_in[8];
    const float* bv   = (const float*)d_in[9];
    const float* Wo   = (const float*)d_in[10];
    const float* bo   = (const float*)d_in[11];
    const float* ln1g = (const float*)d_in[12];
    const float* ln1b = (const float*)d_in[13];
    const float* ln2g = (const float*)d_in[14];
    const float* ln2b = (const float*)d_in[15];
    const float* W1   = (const float*)d_in[16];
    const float* b1   = (const float*)d_in[17];
    const float* W2   = (const float*)d_in[18];
    const float* b2   = (const float*)d_in[19];
    float* out = (float*)d_out;

    float *patch, *enc, *q, *k, *v, *attn, *o, *a, *f1;
    cudaGetSymbolAddress((void**)&patch, g_patch);
    cudaGetSymbolAddress((void**)&enc,   g_enc);
    cudaGetSymbolAddress((void**)&q,     g_q);
    cudaGetSymbolAddress((void**)&k,     g_k);
    cudaGetSymbolAddress((void**)&v,     g_v);
    cudaGetSymbolAddress((void**)&attn,  g_attn);
    cudaGetSymbolAddress((void**)&o,     g_o);
    cudaGetSymbolAddress((void**)&a,     g_a);
    cudaGetSymbolAddress((void**)&f1,    g_f1);

    const float scale = 1.0f / 16.0f;   // 1/sqrt(KD=256)

    patch_embed_kernel<<<(ROWS * D1 + 255) / 256, 256>>>(X, pos, patch);
    launch_gemm(patch, W_in, b_in, enc, ROWS, D1, D1, D1, D1, D1,
                0, 0, 0, 0, 0, 0, 1, 1, 1.f, false, false);

    for (int l = 0; l < LAY; l++) {
        const float* Wq_l = Wq + (long)l * D1 * QC;
        const float* Wk_l = Wk + (long)l * D1 * QC;
        const float* Wv_l = Wv + (long)l * D1 * QC;
        const float* bq_l = bq + (long)l * QC;
        const float* bk_l = bk + (long)l * QC;
        const float* bv_l = bv + (long)l * QC;
        const float* Wo_l = Wo + (long)l * QC * D1;
        const float* bo_l = bo + (long)l * D1;
        const float* W1_l = W1 + (long)l * D1 * HID;
        const float* b1_l = b1 + (long)l * HID;
        const float* W2_l = W2 + (long)l * HID * D1;
        const float* b2_l = b2 + (long)l * D1;

        launch_gemm(enc, Wq_l, bq_l, q, ROWS, QC, D1, D1, QC, QC,
                    0, 0, 0, 0, 0, 0, 1, 1, 1.f, false, false);
        launch_gemm(enc, Wk_l, bk_l, k, ROWS, QC, D1, D1, QC, QC,
                    0, 0, 0, 0, 0, 0, 1, 1, 1.f, false, false);
        launch_gemm(enc, Wv_l, bv_l, v, ROWS, QC, D1, D1, QC, QC,
                    0, 0, 0, 0, 0, 0, 1, 1, 1.f, false, false);

        // logits[b,h,q,n] = scale * Q_bh @ K_bh^T
        launch_gemm(q, k, nullptr, attn, N1, N1, KD, QC, QC, N1,
                    (long)N1 * QC, KD,
                    (long)N1 * QC, KD,
                    (long)NH * N1 * N1, (long)N1 * N1,
                    Bb, NH, scale, true, false);

        softmax_kernel<<<(Bb * NH * N1) / 8, 256>>>(attn, Bb * NH * N1);

        // o[b,q,h,kd] = attn @ V_bh
        launch_gemm(attn, v, nullptr, o, N1, KD, N1, N1, QC, QC,
                    (long)NH * N1 * N1, (long)N1 * N1,
                    (long)N1 * QC, KD,
                    (long)N1 * QC, KD,
                    Bb, NH, 1.f, false, false);

        launch_gemm(o, Wo_l, bo_l, a, ROWS, D1, QC, QC, D1, D1,
                    0, 0, 0, 0, 0, 0, 1, 1, 1.f, false, false);

        add_ln_kernel<<<ROWS / 8, 256>>>(enc, a, ln1g + l * D1, ln1b + l * D1);

        launch_gemm(enc, W1_l, b1_l, f1, ROWS, HID, D1, D1, HID, HID,
                    0, 0, 0, 0, 0, 0, 1, 1, 1.f, false, true);
        launch_gemm(f1, W2_l, b2_l, a, ROWS, D1, HID, HID, D1, D1,
                    0, 0, 0, 0, 0, 0, 1, 1, 1.f, false, true);

        add_ln_kernel<<<ROWS / 8, 256>>>(enc, a, ln2g + l * D1, ln2b + l * D1);
    }

    resample_kernel<<<(Bb * 1024 * 64 + 255) / 256, 256>>>(enc, out);
}

// round 10
// speedup vs baseline: 3.2057x; 1.1132x over previous
#include <cuda_runtime.h>
#include <math.h>
#include <stdint.h>

// ---------------- problem constants ----------------
constexpr int Bb   = 32;
constexpr int N1   = 256;
constexpr int D1   = 256;
constexpr int NH   = 8;
constexpr int KD   = 256;
constexpr int HID  = 1024;
constexpr int LAY  = 8;
constexpr int ROWS = Bb * N1;      // 8192
constexpr int QC   = NH * KD;      // 2048
constexpr float LN_EPS = 1e-3f;

// ---------------- scratch (static device memory; no allocation) ----------------
__device__ float g_patch[ROWS * D1];
__device__ float g_enc  [ROWS * D1];
__device__ float g_encr [ROWS * D1];         // tf32-rounded copy of enc (GEMM A operand)
__device__ float g_q    [ROWS * QC];
__device__ float g_k    [ROWS * QC];
__device__ float g_v    [ROWS * QC];
__device__ float g_attn [Bb * NH * N1 * N1];
__device__ float g_o    [ROWS * QC];
__device__ float g_a    [ROWS * D1];
__device__ float g_f1   [ROWS * HID];
// tf32-rounded weights (refreshed every call)
__device__ float g_wr_in[D1 * D1];
__device__ float g_wr_q [LAY * D1 * QC];
__device__ float g_wr_k [LAY * D1 * QC];
__device__ float g_wr_v [LAY * D1 * QC];
__device__ float g_wr_o [LAY * QC * D1];
__device__ float g_wr_1 [LAY * D1 * HID];
__device__ float g_wr_2 [LAY * HID * D1];

// ---------------- helpers ----------------
__device__ __forceinline__ float gelu_exact(float x) {
    return 0.5f * x * (1.0f + erff(x * 0.7071067811865476f));
}
__device__ __forceinline__ uint32_t f2tf32(float x) {
    uint32_t r;
    asm("cvt.rna.tf32.f32 %0, %1;" : "=r"(r) : "f"(x));
    return r;
}
__device__ __forceinline__ float roundtf(float x) {
    return __uint_as_float(f2tf32(x));
}
__device__ __forceinline__ void mma_tf32(float c[4], const uint32_t a[4], const uint32_t b[2]) {
    asm volatile(
        "mma.sync.aligned.m16n8k8.row.col.f32.tf32.tf32.f32 "
        "{%0,%1,%2,%3}, {%4,%5,%6,%7}, {%8,%9}, {%0,%1,%2,%3};\n"
        : "+f"(c[0]), "+f"(c[1]), "+f"(c[2]), "+f"(c[3])
        : "r"(a[0]), "r"(a[1]), "r"(a[2]), "r"(a[3]),
          "r"(b[0]), "r"(b[1]));
}
__device__ __forceinline__ void cp_async16(uint32_t dst_smem, const void* src) {
    asm volatile("cp.async.cg.shared.global [%0], [%1], 16;" :: "r"(dst_smem), "l"(src));
}
__device__ __forceinline__ void cp_commit() {
    asm volatile("cp.async.commit_group;" ::: "memory");
}
template<int N>
__device__ __forceinline__ void cp_wait() {
    asm volatile("cp.async.wait_group %0;" :: "n"(N) : "memory");
}

// ---------------- TF32 tensor-core GEMM: inputs pre-rounded, BK=32, cp.async x2 ----------------
// C[z] = act( alpha * A[z] @ op(B[z]) + bias ); all A/B elements already tf32-rounded.
// A: [M,K] row-major.  NN: B [K,N];  NT: B [N,K] (computes A.B^T)
// Block 128x128x32, 8 warps (2m x 4n), warp tile 64x32, mma m16n8k8.
// OMODE: 0 = store full fp32; 1 = store tf32-rounded; 2 = dual (C full, Cr rounded)
#define BM 128
#define BN 128
#define BK 32
#define AS_LD 36      // [m][k] stride 36 floats: bank = 4*qrow+qcol, conflict-free; 16B-aligned
#define BS_LD 136     // NN [k][n] stride 136: bank = 8*qcol+qrow (+8u), conflict-free
#define A_STG 4608    // 128*36 floats per A stage
#define B_STG 4608    // max(32*136=4352, 128*36=4608) floats per B stage
#define SMEM_GEMM ((2 * A_STG + 2 * B_STG) * 4)   // 73728 bytes

template<bool TRANS_B, bool GELU, int OMODE>
__global__ __launch_bounds__(256, 2)
void mma_gemm_kernel(const float* __restrict__ A, const float* __restrict__ B,
                     const float* __restrict__ bias, float* __restrict__ C,
                     float* __restrict__ Cr,
                     int K, int lda, int ldb, int ldc,
                     long sA1, long sA2, long sB1, long sB2, long sC1, long sC2,
                     int nb2, float alpha)
{
    extern __shared__ float smem[];
    const int z  = blockIdx.z;
    const int z1 = z / nb2, z2 = z - z1 * nb2;
    A += (long)z1 * sA1 + (long)z2 * sA2;
    B += (long)z1 * sB1 + (long)z2 * sB2;
    C += (long)z1 * sC1 + (long)z2 * sC2;
    if (OMODE == 2) Cr += (long)z1 * sC1 + (long)z2 * sC2;

    const int tid  = threadIdx.x;
    const int lane = tid & 31;
    const int wid  = tid >> 5;
    const int wm   = wid >> 2;           // 0..1
    const int wn   = wid & 3;            // 0..3
    const int row0 = blockIdx.y * BM;
    const int col0 = blockIdx.x * BN;

    // loaders: 4x cp.async16 per thread per operand stage
    const int a_row = tid >> 3;          // 0..31
    const int a_col = (tid & 7) << 2;    // 0,4,...,28
    const int b_row = tid >> 5;          // 0..7
    const int b_col = (tid & 31) << 2;   // 0..124

    const int qrow = lane >> 2;          // 0..7
    const int qcol = lane & 3;           // 0..3

    const uint32_t sbase = (uint32_t)__cvta_generic_to_shared(smem);
    // float offsets of the 4 regions
    const uint32_t offA[2] = {0u, A_STG};
    const uint32_t offB[2] = {2u * A_STG, 2u * A_STG + B_STG};

    float acc[4][4][4];
#pragma unroll
    for (int t = 0; t < 4; t++)
#pragma unroll
        for (int u = 0; u < 4; u++)
#pragma unroll
            for (int r = 0; r < 4; r++) acc[t][u][r] = 0.f;

    const int steps = K >> 5;            // K multiple of 32; min 8

    auto fill = [&](int buf, int k0) {
#pragma unroll
        for (int r = 0; r < 4; r++) {
            int m = a_row + r * 32;
            cp_async16(sbase + (offA[buf] + (uint32_t)(m * AS_LD + a_col)) * 4,
                       A + (long)(row0 + m) * lda + k0 + a_col);
        }
        if (!TRANS_B) {
#pragma unroll
            for (int r = 0; r < 4; r++) {
                int kk = b_row + r * 8;
                cp_async16(sbase + (offB[buf] + (uint32_t)(kk * BS_LD + b_col)) * 4,
                           B + (long)(k0 + kk) * ldb + col0 + b_col);
            }
        } else {
#pragma unroll
            for (int r = 0; r < 4; r++) {
                int n = a_row + r * 32;
                cp_async16(sbase + (offB[buf] + (uint32_t)(n * AS_LD + a_col)) * 4,
                           B + (long)(col0 + n) * ldb + k0 + a_col);
            }
        }
    };

    fill(0, 0);     cp_commit();
    fill(1, BK);    cp_commit();

    for (int s = 0; s < steps; s++) {
        if (s + 1 < steps) cp_wait<1>(); else cp_wait<0>();
        __syncthreads();
        const float* Ab   = smem + offA[s & 1];
        const float* Bbuf = smem + offB[s & 1];

#pragma unroll
        for (int ks = 0; ks < BK; ks += 8) {
            uint32_t afrag[4][4];
#pragma unroll
            for (int t = 0; t < 4; t++) {
                int mb = wm * 64 + t * 16;
                afrag[t][0] = __float_as_uint(Ab[(mb + qrow)     * AS_LD + ks + qcol    ]);
                afrag[t][1] = __float_as_uint(Ab[(mb + qrow + 8) * AS_LD + ks + qcol    ]);
                afrag[t][2] = __float_as_uint(Ab[(mb + qrow)     * AS_LD + ks + qcol + 4]);
                afrag[t][3] = __float_as_uint(Ab[(mb + qrow + 8) * AS_LD + ks + qcol + 4]);
            }
            uint32_t bfrag[4][2];
#pragma unroll
            for (int u = 0; u < 4; u++) {
                int nb = wn * 32 + u * 8;
                if (!TRANS_B) {
                    bfrag[u][0] = __float_as_uint(Bbuf[(ks + qcol)     * BS_LD + nb + qrow]);
                    bfrag[u][1] = __float_as_uint(Bbuf[(ks + qcol + 4) * BS_LD + nb + qrow]);
                } else {
                    bfrag[u][0] = __float_as_uint(Bbuf[(nb + qrow) * AS_LD + ks + qcol    ]);
                    bfrag[u][1] = __float_as_uint(Bbuf[(nb + qrow) * AS_LD + ks + qcol + 4]);
                }
            }
#pragma unroll
            for (int t = 0; t < 4; t++)
#pragma unroll
                for (int u = 0; u < 4; u++)
                    mma_tf32(acc[t][u], afrag[t], bfrag[u]);
        }
        __syncthreads();
        if (s + 2 < steps) { fill(s & 1, (s + 2) << 5); cp_commit(); }
    }

    // ---- epilogue ----
#pragma unroll
    for (int t = 0; t < 4; t++) {
        int r0 = row0 + wm * 64 + t * 16 + qrow;
#pragma unroll
        for (int u = 0; u < 4; u++) {
            int n = col0 + wn * 32 + u * 8 + qcol * 2;
            float bx = bias ? bias[n + 0] : 0.f;
            float by = bias ? bias[n + 1] : 0.f;
            float2 v0, v1;
            v0.x = fmaf(acc[t][u][0], alpha, bx);
            v0.y = fmaf(acc[t][u][1], alpha, by);
            v1.x = fmaf(acc[t][u][2], alpha, bx);
            v1.y = fmaf(acc[t][u][3], alpha, by);
            if (GELU) {
                v0.x = gelu_exact(v0.x); v0.y = gelu_exact(v0.y);
                v1.x = gelu_exact(v1.x); v1.y = gelu_exact(v1.y);
            }
            if (OMODE == 1) {
                v0.x = roundtf(v0.x); v0.y = roundtf(v0.y);
                v1.x = roundtf(v1.x); v1.y = roundtf(v1.y);
            }
            *(float2*)(C + (long)r0 * ldc + n)       = v0;
            *(float2*)(C + (long)(r0 + 8) * ldc + n) = v1;
            if (OMODE == 2) {
                float2 w0, w1;
                w0.x = roundtf(v0.x); w0.y = roundtf(v0.y);
                w1.x = roundtf(v1.x); w1.y = roundtf(v1.y);
                *(float2*)(Cr + (long)r0 * ldc + n)       = w0;
                *(float2*)(Cr + (long)(r0 + 8) * ldc + n) = w1;
            }
        }
    }
}

// ---------------- tf32 round-copy (weights) ----------------
__global__ void round_copy_kernel(const float* __restrict__ in, float* __restrict__ out, int n)
{
    int i = blockIdx.x * blockDim.x + threadIdx.x;
    if (i < n) out[i] = roundtf(in[i]);
}

// ---------------- patchify + pos-emb (tf32-rounded output) ----------------
__global__ void patch_embed_kernel(const float* __restrict__ X,
                                   const float* __restrict__ pos,
                                   float* __restrict__ P)
{
    int i = blockIdx.x * blockDim.x + threadIdx.x;
    if (i >= ROWS * D1) return;
    int b   = i >> 16;
    int rem = i & 65535;
    int n   = rem >> 8;
    int d   = rem & 255;
    int gy = n >> 4, gx = n & 15;
    int py = d >> 4, px = d & 15;
    int y = gy * 16 + py, x = gx * 16 + px;
    P[i] = roundtf(X[((long)(b * 256 + y)) * 256 + x] + pos[n * 256 + d]);
}

// ---------------- softmax over rows of 256 (tf32-rounded output) ----------------
__global__ void softmax_kernel(float* __restrict__ A, int nrows)
{
    int row  = blockIdx.x * (blockDim.x >> 5) + (threadIdx.x >> 5);
    if (row >= nrows) return;
    int lane = threadIdx.x & 31;
    float* p = A + (long)row * 256;
    float v[8];
    float mx = -INFINITY;
#pragma unroll
    for (int i = 0; i < 8; i++) { v[i] = p[lane + i * 32]; mx = fmaxf(mx, v[i]); }
#pragma unroll
    for (int o = 16; o > 0; o >>= 1) mx = fmaxf(mx, __shfl_xor_sync(0xffffffffu, mx, o));
    float s = 0.f;
#pragma unroll
    for (int i = 0; i < 8; i++) { v[i] = __expf(v[i] - mx); s += v[i]; }
#pragma unroll
    for (int o = 16; o > 0; o >>= 1) s += __shfl_xor_sync(0xffffffffu, s, o);
    float r = 1.f / s;
#pragma unroll
    for (int i = 0; i < 8; i++) p[lane + i * 32] = roundtf(v[i] * r);
}

// ---------------- residual add + LayerNorm; writes full enc and rounded enc_r ----------------
__global__ void add_ln_kernel(float* __restrict__ enc, float* __restrict__ encr,
                              const float* __restrict__ res,
                              const float* __restrict__ g, const float* __restrict__ bta)
{
    int row  = blockIdx.x * (blockDim.x >> 5) + (threadIdx.x >> 5);
    if (row >= ROWS) return;
    int lane = threadIdx.x & 31;
    float* pe = enc + (long)row * 256;
    float* pr2 = encr + (long)row * 256;
    const float* pr = res + (long)row * 256;
    float v[8];
    float s = 0.f;
#pragma unroll
    for (int i = 0; i < 8; i++) { v[i] = pe[lane + i * 32] + pr[lane + i * 32]; s += v[i]; }
#pragma unroll
    for (int o = 16; o > 0; o >>= 1) s += __shfl_xor_sync(0xffffffffu, s, o);
    float mu = s * (1.f / 256.f);
    float q = 0.f;
#pragma unroll
    for (int i = 0; i < 8; i++) { float d = v[i] - mu; q += d * d; }
#pragma unroll
    for (int o = 16; o > 0; o >>= 1) q += __shfl_xor_sync(0xffffffffu, q, o);
    float inv = rsqrtf(q * (1.f / 256.f) + LN_EPS);
#pragma unroll
    for (int i = 0; i < 8; i++) {
        int d = lane + i * 32;
        float w = (v[i] - mu) * inv * g[d] + bta[d];
        pe[d] = w;
        pr2[d] = roundtf(w);
    }
}

// ---------------- final resample: unpatch(16) -> patchify(8) ----------------
__global__ void resample_kernel(const float* __restrict__ enc, float* __restrict__ out)
{
    int i = blockIdx.x * blockDim.x + threadIdx.x;
    if (i >= Bb * 1024 * 64) return;
    int b   = i >> 16;
    int rem = i & 65535;
    int n2  = rem >> 6;
    int d2  = rem & 63;
    int gy2 = n2 >> 5, gx2 = n2 & 31;
    int py2 = d2 >> 3, px2 = d2 & 7;
    int y = gy2 * 8 + py2, x = gx2 * 8 + px2;
    int n1 = (y >> 4) * 16 + (x >> 4);
    int d1 = (y & 15) * 16 + (x & 15);
    out[i] = enc[((long)(b * 256 + n1)) * 256 + d1];
}

extern "C" void kernel_launch(void* const* d_in, const int* in_sizes, int n_in,
                              void* d_out, int out_size)
{
    (void)in_sizes; (void)n_in; (void)out_size;
    const float* X    = (const float*)d_in[0];
    const float* pos  = (const float*)d_in[1];
    const float* W_in = (const float*)d_in[2];
    const float* b_in = (const float*)d_in[3];
    const float* Wq   = (const float*)d_in[4];
    const float* bq   = (const float*)d_in[5];
    const float* Wk   = (const float*)d_in[6];
    const float* bk   = (const float*)d_in[7];
    const float* Wv   = (const float*)d_in[8];
    const float* bv   = (const float*)d_in[9];
    const float* Wo   = (const float*)d_in[10];
    const float* bo   = (const float*)d_in[11];
    const float* ln1g = (const float*)d_in[12];
    const float* ln1b = (const float*)d_in[13];
    const float* ln2g = (const float*)d_in[14];
    const float* ln2b = (const float*)d_in[15];
    const float* W1   = (const float*)d_in[16];
    const float* b1   = (const float*)d_in[17];
    const float* W2   = (const float*)d_in[18];
    const float* b2   = (const float*)d_in[19];
    float* out = (float*)d_out;

    float *patch, *enc, *encr, *q, *k, *v, *attn, *o, *a, *f1;
    float *wrin, *wrq, *wrk, *wrv, *wro, *wr1, *wr2;
    cudaGetSymbolAddress((void**)&patch, g_patch);
    cudaGetSymbolAddress((void**)&enc,   g_enc);
    cudaGetSymbolAddress((void**)&encr,  g_encr);
    cudaGetSymbolAddress((void**)&q,     g_q);
    cudaGetSymbolAddress((void**)&k,     g_k);
    cudaGetSymbolAddress((void**)&v,     g_v);
    cudaGetSymbolAddress((void**)&attn,  g_attn);
    cudaGetSymbolAddress((void**)&o,     g_o);
    cudaGetSymbolAddress((void**)&a,     g_a);
    cudaGetSymbolAddress((void**)&f1,    g_f1);
    cudaGetSymbolAddress((void**)&wrin,  g_wr_in);
    cudaGetSymbolAddress((void**)&wrq,   g_wr_q);
    cudaGetSymbolAddress((void**)&wrk,   g_wr_k);
    cudaGetSymbolAddress((void**)&wrv,   g_wr_v);
    cudaGetSymbolAddress((void**)&wro,   g_wr_o);
    cudaGetSymbolAddress((void**)&wr1,   g_wr_1);
    cudaGetSymbolAddress((void**)&wr2,   g_wr_2);

    cudaFuncSetAttribute(mma_gemm_kernel<false, false, 0>, cudaFuncAttributeMaxDynamicSharedMemorySize, SMEM_GEMM);
    cudaFuncSetAttribute(mma_gemm_kernel<false, false, 1>, cudaFuncAttributeMaxDynamicSharedMemorySize, SMEM_GEMM);
    cudaFuncSetAttribute(mma_gemm_kernel<false, false, 2>, cudaFuncAttributeMaxDynamicSharedMemorySize, SMEM_GEMM);
    cudaFuncSetAttribute(mma_gemm_kernel<true,  false, 0>, cudaFuncAttributeMaxDynamicSharedMemorySize, SMEM_GEMM);
    cudaFuncSetAttribute(mma_gemm_kernel<false, true,  0>, cudaFuncAttributeMaxDynamicSharedMemorySize, SMEM_GEMM);
    cudaFuncSetAttribute(mma_gemm_kernel<false, true,  1>, cudaFuncAttributeMaxDynamicSharedMemorySize, SMEM_GEMM);

    const float scale = 1.0f / 16.0f;   // 1/sqrt(KD=256)

    // ---- pre-round all weights to tf32 (numerics-identical to per-consume cvt) ----
    round_copy_kernel<<<(D1 * D1 + 255) / 256, 256>>>(W_in, wrin, D1 * D1);
    round_copy_kernel<<<(LAY * D1 * QC + 255) / 256, 256>>>(Wq, wrq, LAY * D1 * QC);
    round_copy_kernel<<<(LAY * D1 * QC + 255) / 256, 256>>>(Wk, wrk, LAY * D1 * QC);
    round_copy_kernel<<<(LAY * D1 * QC + 255) / 256, 256>>>(Wv, wrv, LAY * D1 * QC);
    round_copy_kernel<<<(LAY * QC * D1 + 255) / 256, 256>>>(Wo, wro, LAY * QC * D1);
    round_copy_kernel<<<(LAY * D1 * HID + 255) / 256, 256>>>(W1, wr1, LAY * D1 * HID);
    round_copy_kernel<<<(LAY * HID * D1 + 255) / 256, 256>>>(W2, wr2, LAY * HID * D1);

    patch_embed_kernel<<<(ROWS * D1 + 255) / 256, 256>>>(X, pos, patch);

    // enc = patch @ W_in + b_in  (dual: full enc + rounded encr)
    mma_gemm_kernel<false, false, 2><<<dim3(D1 / BN, ROWS / BM, 1), 256, SMEM_GEMM>>>(
        patch, wrin, b_in, enc, encr, D1, D1, D1, D1, 0, 0, 0, 0, 0, 0, 1, 1.f);

    for (int l = 0; l < LAY; l++) {
        const float* wq_l = wrq + (long)l * D1 * QC;
        const float* wk_l = wrk + (long)l * D1 * QC;
        const float* wv_l = wrv + (long)l * D1 * QC;
        const float* wo_l = wro + (long)l * QC * D1;
        const float* w1_l = wr1 + (long)l * D1 * HID;
        const float* w2_l = wr2 + (long)l * HID * D1;

        // q,k,v = encr @ W + b  (rounded outputs; consumed only by GEMMs)
        mma_gemm_kernel<false, false, 1><<<dim3(QC / BN, ROWS / BM, 1), 256, SMEM_GEMM>>>(
            encr, wq_l, bq + (long)l * QC, q, nullptr, D1, D1, QC, QC, 0, 0, 0, 0, 0, 0, 1, 1.f);
        mma_gemm_kernel<false, false, 1><<<dim3(QC / BN, ROWS / BM, 1), 256, SMEM_GEMM>>>(
            encr, wk_l, bk + (long)l * QC, k, nullptr, D1, D1, QC, QC, 0, 0, 0, 0, 0, 0, 1, 1.f);
        mma_gemm_kernel<false, false, 1><<<dim3(QC / BN, ROWS / BM, 1), 256, SMEM_GEMM>>>(
            encr, wv_l, bv + (long)l * QC, v, nullptr, D1, D1, QC, QC, 0, 0, 0, 0, 0, 0, 1, 1.f);

        // logits[b,h,q,n] = scale * Q_bh @ K_bh^T  (full precision for softmax)
        mma_gemm_kernel<true, false, 0><<<dim3(N1 / BN, N1 / BM, Bb * NH), 256, SMEM_GEMM>>>(
            q, k, nullptr, attn, nullptr, KD, QC, QC, N1,
            (long)N1 * QC, KD, (long)N1 * QC, KD,
            (long)NH * N1 * N1, (long)N1 * N1, NH, scale);

        softmax_kernel<<<(Bb * NH * N1) / 8, 256>>>(attn, Bb * NH * N1);

        // o = attn @ V  (rounded; consumed only by Wo GEMM)
        mma_gemm_kernel<false, false, 1><<<dim3(KD / BN, N1 / BM, Bb * NH), 256, SMEM_GEMM>>>(
            attn, v, nullptr, o, nullptr, N1, N1, QC, QC,
            (long)NH * N1 * N1, (long)N1 * N1,
            (long)N1 * QC, KD,
            (long)N1 * QC, KD, NH, 1.f);

        // a = o @ Wo + bo  (full; consumed by add_ln)
        mma_gemm_kernel<false, false, 0><<<dim3(D1 / BN, ROWS / BM, 1), 256, SMEM_GEMM>>>(
            o, wo_l, bo + (long)l * D1, a, nullptr, QC, QC, D1, D1, 0, 0, 0, 0, 0, 0, 1, 1.f);

        add_ln_kernel<<<ROWS / 8, 256>>>(enc, encr, a, ln1g + (long)l * D1, ln1b + (long)l * D1);

        // f1 = gelu(encr @ W1 + b1)  (rounded; consumed by W2 GEMM)
        mma_gemm_kernel<false, true, 1><<<dim3(HID / BN, ROWS / BM, 1), 256, SMEM_GEMM>>>(
            encr, w1_l, b1 + (long)l * HID, f1, nullptr, D1, D1, HID, HID, 0, 0, 0, 0, 0, 0, 1, 1.f);
        // f2 = gelu(f1 @ W2 + b2)  (full; consumed by add_ln)
        mma_gemm_kernel<false, true, 0><<<dim3(D1 / BN, ROWS / BM, 1), 256, SMEM_GEMM>>>(
            f1, w2_l, b2 + (long)l * D1, a, nullptr, HID, HID, D1, D1, 0, 0, 0, 0, 0, 0, 1, 1.f);

        add_ln_kernel<<<ROWS / 8, 256>>>(enc, encr, a, ln2g + (long)l * D1, ln2b + (long)l * D1);
    }

    resample_kernel<<<(Bb * 1024 * 64 + 255) / 256, 256>>>(enc, out);
}